// round 9
// baseline (speedup 1.0000x reference)
#include <cuda_runtime.h>
#include <cuda_bf16.h>
#include <cstdint>
#include <cstring>

#define TS   512
#define BSZ  256
#define DIN  256
#define HID  256
#define OUTD 64
#define MROWS (TS * BSZ)
#define NCTA_S 128           // serial kernel CTAs: 16 groups x 8 col-CTAs
#define PA   260             // sA pitch (floats): 1040B -> rows offset 16B in bank space
#define PAK  40              // xw_mma staged tile pitch in bf16

// serial-kernel smem: sW [256][128] + sA [16][PA]
#define SW_F   (256 * 128)
#define SA_F   (16 * PA)
#define SMEM_SERIAL ((SW_F + SA_F) * 4)        // 147,712 B

// xw_mma smem layout (bytes)
#define OFF_BIAS 0
#define OFF_AH   1024
#define OFF_AL   (OFF_AH + 128 * PAK * 2)
#define OFF_BH   (OFF_AL + 128 * PAK * 2)
#define OFF_BL   (OFF_BH + 128 * PAK * 2)
#define SMEM_MMA (OFF_BL + 128 * PAK * 2)      // 41984 B

extern __shared__ char smem_dyn[];

__device__ float          g_xwb[(size_t)MROWS * 1024];   // x@Wx + b, [m][g*256+j]
__device__ __nv_bfloat16  g_ah[(size_t)MROWS * DIN];
__device__ __nv_bfloat16  g_al[(size_t)MROWS * DIN];
__device__ __nv_bfloat16  g_wth[1024 * 256];              // W^T hi [n][k]
__device__ __nv_bfloat16  g_wtl[1024 * 256];              // W^T lo
__device__ float          g_hbuf[2][BSZ * HID];
__device__ unsigned       g_rbar[16][64];                 // per-row-group barriers (256B apart)
__device__ unsigned       g_bar;                          // final global barrier

typedef unsigned long long u64;

__device__ __forceinline__ u64 ffma2(u64 a, u64 b, u64 c) {
    u64 d; asm("fma.rn.f32x2 %0, %1, %2, %3;" : "=l"(d) : "l"(a), "l"(b), "l"(c)); return d;
}
__device__ __forceinline__ u64 dup2(float a) {
    u64 d; asm("mov.b64 %0, {%1, %1};" : "=l"(d) : "f"(a)); return d;
}
__device__ __forceinline__ u64 pack2f(float lo, float hi) {
    u64 d; asm("mov.b64 %0, {%1, %2};" : "=l"(d) : "f"(lo), "f"(hi)); return d;
}
__device__ __forceinline__ void unpack2f(u64 v, float& lo, float& hi) {
    asm("mov.b64 {%0, %1}, %2;" : "=f"(lo), "=f"(hi) : "l"(v));
}
__device__ __forceinline__ float sigmoidf_(float x) { return 1.0f / (1.0f + __expf(-x)); }
__device__ __forceinline__ float tanhf_(float x) {
    float e = __expf(2.0f * x); return 1.0f - 2.0f / (e + 1.0f);
}
__device__ __forceinline__ uint32_t s2u(const void* p) {
    uint32_t a; asm("{ .reg .u64 t; cvta.to.shared.u64 t, %1; cvt.u32.u64 %0, t; }" : "=r"(a) : "l"(p));
    return a;
}
__device__ __forceinline__ uint32_t pack2(float a, float b) {
    __nv_bfloat162 t; t.x = __float2bfloat16(a); t.y = __float2bfloat16(b);
    uint32_t r; memcpy(&r, &t, 4); return r;
}
__device__ __forceinline__ void arrive_release(unsigned* ctr) {
    asm volatile("red.release.gpu.global.add.u32 [%0], %1;" :: "l"(ctr), "r"(1u) : "memory");
}
__device__ __forceinline__ void wait_target(const unsigned* ctr, unsigned tgt) {
    unsigned v;
    do {
        asm volatile("ld.global.acquire.gpu.u32 %0, [%1];" : "=r"(v) : "l"(ctr));
        if (v >= tgt) break;
        __nanosleep(20);
    } while (true);
}

#define LDSM4(d0, d1, d2, d3, addr) \
    asm volatile("ldmatrix.sync.aligned.m8n8.x4.shared.b16 {%0,%1,%2,%3}, [%4];" \
                 : "=r"(d0), "=r"(d1), "=r"(d2), "=r"(d3) : "r"(addr))

#define MMA16816(c, a, b0, b1) \
    asm volatile("mma.sync.aligned.m16n8k16.row.col.f32.bf16.bf16.f32 " \
                 "{%0,%1,%2,%3}, {%4,%5,%6,%7}, {%8,%9}, {%0,%1,%2,%3};" \
                 : "+f"((c)[0]), "+f"((c)[1]), "+f"((c)[2]), "+f"((c)[3]) \
                 : "r"((a)[0]), "r"((a)[1]), "r"((a)[2]), "r"((a)[3]), "r"(b0), "r"(b1))

// ---------------- conversions ----------------
__global__ void convert_x(const float* __restrict__ x) {
    size_t i = (size_t)blockIdx.x * 256 + threadIdx.x;
    float4 v = ((const float4*)x)[i];
    float h0 = __bfloat162float(__float2bfloat16(v.x));
    float h1 = __bfloat162float(__float2bfloat16(v.y));
    float h2 = __bfloat162float(__float2bfloat16(v.z));
    float h3 = __bfloat162float(__float2bfloat16(v.w));
    uint2 ph, pl;
    ph.x = pack2(v.x, v.y); ph.y = pack2(v.z, v.w);
    pl.x = pack2(v.x - h0, v.y - h1); pl.y = pack2(v.z - h2, v.w - h3);
    ((uint2*)g_ah)[i] = ph;
    ((uint2*)g_al)[i] = pl;
}

__global__ void convert_w(const float* __restrict__ Wf, const float* __restrict__ Wi,
                          const float* __restrict__ Wc, const float* __restrict__ Wo) {
    int n = blockIdx.x, k = threadIdx.x;
    int g = n >> 8, j = n & 255;
    const float* Wg = (g == 0) ? Wf : (g == 1) ? Wi : (g == 2) ? Wc : Wo;
    float v = Wg[(size_t)k * HID + j];
    float h = __bfloat162float(__float2bfloat16(v));
    g_wth[n * 256 + k] = __float2bfloat16(v);
    g_wtl[n * 256 + k] = __float2bfloat16(v - h);
}

// ---------------- xwb = x @ Wx + b via mma.sync bf16 3-term split ----------------
__global__ void __launch_bounds__(256) xw_mma(
    const float* __restrict__ bfp, const float* __restrict__ bip,
    const float* __restrict__ bcp, const float* __restrict__ bop)
{
    char* sm = smem_dyn;
    float* sBias = (float*)(sm + OFF_BIAS);
    const uint32_t uAh = s2u(sm + OFF_AH);
    const uint32_t uAl = s2u(sm + OFF_AL);
    const uint32_t uBh = s2u(sm + OFF_BH);
    const uint32_t uBl = s2u(sm + OFF_BL);

    const int tid  = threadIdx.x;
    const int w    = tid >> 5;
    const int lane = tid & 31;
    const int wm   = w & 3;
    const int wn   = w >> 2;
    const int n0   = blockIdx.x * 128;
    const int m0   = blockIdx.y * 128;

    if (tid < 128) {
        int g = n0 >> 8;
        const float* bg = (g == 0) ? bfp : (g == 1) ? bip : (g == 2) ? bcp : bop;
        sBias[tid] = bg[(n0 & 255) + tid];
    }

    const int arow  = lane & 15;
    const int ahalf = (lane >> 4) & 1;
    const int brow  = ((lane >> 4) & 1) * 8 + (lane & 7);
    const int bcol  = ((lane >> 3) & 1) * 8;

    float c[2][8][4];
    #pragma unroll
    for (int mt = 0; mt < 2; ++mt)
        #pragma unroll
        for (int nt = 0; nt < 8; ++nt)
            #pragma unroll
            for (int q = 0; q < 4; ++q) c[mt][nt][q] = 0.f;

    for (int ck = 0; ck < 8; ++ck) {
        const int k0 = ck * 32;
        __syncthreads();
        #pragma unroll
        for (int it = 0; it < 2; ++it) {
            int idx = tid + it * 256;
            int r = idx >> 2, cq = idx & 3;
            uint32_t doff = (uint32_t)(r * (PAK * 2) + cq * 16);
            *(uint4*)(sm + OFF_AH + doff) = *(const uint4*)(g_ah  + (size_t)(m0 + r) * 256 + k0 + cq * 8);
            *(uint4*)(sm + OFF_AL + doff) = *(const uint4*)(g_al  + (size_t)(m0 + r) * 256 + k0 + cq * 8);
            *(uint4*)(sm + OFF_BH + doff) = *(const uint4*)(g_wth + (size_t)(n0 + r) * 256 + k0 + cq * 8);
            *(uint4*)(sm + OFF_BL + doff) = *(const uint4*)(g_wtl + (size_t)(n0 + r) * 256 + k0 + cq * 8);
        }
        __syncthreads();

        #pragma unroll
        for (int ks = 0; ks < 2; ++ks) {
            const int kk = ks * 16;
            uint32_t ah[2][4], al[2][4];
            #pragma unroll
            for (int mt = 0; mt < 2; ++mt) {
                uint32_t ao = (uint32_t)((wm * 32 + mt * 16 + arow) * (PAK * 2) + (kk + ahalf * 8) * 2);
                LDSM4(ah[mt][0], ah[mt][1], ah[mt][2], ah[mt][3], uAh + ao);
                LDSM4(al[mt][0], al[mt][1], al[mt][2], al[mt][3], uAl + ao);
            }
            #pragma unroll
            for (int np = 0; np < 4; ++np) {
                uint32_t bo = (uint32_t)((wn * 64 + np * 16 + brow) * (PAK * 2) + (kk + bcol) * 2);
                uint32_t bh[4], bl[4];
                LDSM4(bh[0], bh[1], bh[2], bh[3], uBh + bo);
                LDSM4(bl[0], bl[1], bl[2], bl[3], uBl + bo);
                #pragma unroll
                for (int mt = 0; mt < 2; ++mt) {
                    MMA16816(c[mt][2 * np],     ah[mt], bh[0], bh[1]);
                    MMA16816(c[mt][2 * np + 1], ah[mt], bh[2], bh[3]);
                    MMA16816(c[mt][2 * np],     ah[mt], bl[0], bl[1]);
                    MMA16816(c[mt][2 * np + 1], ah[mt], bl[2], bl[3]);
                    MMA16816(c[mt][2 * np],     al[mt], bh[0], bh[1]);
                    MMA16816(c[mt][2 * np + 1], al[mt], bh[2], bh[3]);
                }
            }
        }
    }

    const int g  = lane >> 2;
    const int tg = lane & 3;
    float* base = g_xwb + (size_t)(m0 + wm * 32) * 1024 + n0 + wn * 64;
    #pragma unroll
    for (int mt = 0; mt < 2; ++mt) {
        #pragma unroll
        for (int nt = 0; nt < 8; ++nt) {
            float2 bv = *(float2*)&sBias[wn * 64 + nt * 8 + 2 * tg];
            float2 v0, v1;
            v0.x = c[mt][nt][0] + bv.x; v0.y = c[mt][nt][1] + bv.y;
            v1.x = c[mt][nt][2] + bv.x; v1.y = c[mt][nt][3] + bv.y;
            *(float2*)(base + (size_t)(mt * 16 + g)     * 1024 + nt * 8 + 2 * tg) = v0;
            *(float2*)(base + (size_t)(mt * 16 + g + 8) * 1024 + nt * 8 + 2 * tg) = v1;
        }
    }
}

// ---------------- init ----------------
__global__ void init_state() {
    int i = blockIdx.x * blockDim.x + threadIdx.x;
    if (i == 0) g_bar = 0u;
    if (i < 16 * 64) ((unsigned*)g_rbar)[i] = 0u;
    if (i < BSZ * HID / 4) ((float4*)g_hbuf[0])[i] = make_float4(0.f, 0.f, 0.f, 0.f);
}

// ---------------- serial loop: h @ Wh, no cross-warp reduction ----------------
// 128 CTAs = 16 row-groups x 8 col-CTAs. CTA: 16 rows x 32 hcols x 4 gates.
// Warp (ro, jo): rows ro*8..+7, jcols jo*8..+7. Lane: rows (ro*8+rthr, +4), jcol jthr.
__global__ void __launch_bounds__(256, 1) lstm_serial(
    const int* __restrict__ lengths,
    const float* __restrict__ Wf, const float* __restrict__ Wi,
    const float* __restrict__ Wc, const float* __restrict__ Wo,
    const float* __restrict__ Wy, const float* __restrict__ by,
    float* __restrict__ out)
{
    float* sm = (float*)smem_dyn;
    float* sW = sm;               // [256][128]: [k][jl][4 gates]
    float* sA = sm + SW_F;        // [16][PA]

    const int tid  = threadIdx.x;
    const int w    = tid >> 5;
    const int lane = tid & 31;
    const int ro   = w >> 2;
    const int jo   = w & 3;
    const int rthr = lane >> 3;
    const int jthr = lane & 7;
    const int bid  = blockIdx.x;
    const int grp  = bid >> 3;
    const int b0   = grp * 16;
    const int j0   = (bid & 7) * 32;
    const int jl   = jo * 8 + jthr;
    const int jg   = j0 + jl;
    const int r0   = ro * 8 + rthr;
    const int r1   = r0 + 4;
    unsigned* myctr = &g_rbar[grp][0];

    // stage W slice once: sW[k][jl][g] = Wg[DIN+k][j0+jl]
    for (int i = tid; i < SW_F; i += 256) {
        int k = i >> 7, q = i & 127;
        int g = q >> 5, jj2 = q & 31;
        const float* __restrict__ Wg = (g == 0) ? Wf : (g == 1) ? Wi : (g == 2) ? Wc : Wo;
        sW[k * 128 + jj2 * 4 + g] = Wg[(size_t)(DIN + k) * HID + j0 + jj2];
    }

    const int len0 = lengths[b0 + r0];
    const int len1 = lengths[b0 + r1];
    float c0 = 0.f, c1 = 0.f, h0 = 0.f, h1 = 0.f;

    for (int t = 0; t < TS; ++t) {
        const float* __restrict__ hprev = g_hbuf[t & 1];
        float*       __restrict__ hnext = g_hbuf[(t + 1) & 1];

        // prefetch xW+b for both rows, all 4 gates; becomes accumulator init
        const float* x0 = g_xwb + ((size_t)t * BSZ + b0 + r0) * 1024 + jg;
        const float* x1 = g_xwb + ((size_t)t * BSZ + b0 + r1) * 1024 + jg;
        u64 accFI0 = pack2f(__ldcg(x0), __ldcg(x0 + 256));
        u64 accCO0 = pack2f(__ldcg(x0 + 512), __ldcg(x0 + 768));
        u64 accFI1 = pack2f(__ldcg(x1), __ldcg(x1 + 256));
        u64 accCO1 = pack2f(__ldcg(x1 + 512), __ldcg(x1 + 768));

        // stage A = h rows b0..b0+15 (16 x 256 floats)
        #pragma unroll
        for (int it = 0; it < 4; ++it) {
            int idx = tid + it * 256;
            int r = idx >> 6, ck = idx & 63;
            float4 v = __ldcg((const float4*)(hprev + (size_t)(b0 + r) * HID + ck * 4));
            *(float4*)(sA + r * PA + ck * 4) = v;
        }
        __syncthreads();

        // GEMM: full K=256 per lane, gates paired in ffma2
        const float* aRow0 = sA + r0 * PA;
        const float* aRow1 = sA + r1 * PA;
        const float* wCol  = sW + jl * 4;
        #pragma unroll 8
        for (int kb = 0; kb < 64; ++kb) {
            float4 a0 = *(const float4*)(aRow0 + kb * 4);
            float4 a1 = *(const float4*)(aRow1 + kb * 4);
            #pragma unroll
            for (int kk = 0; kk < 4; ++kk) {
                ulonglong2 wv = *(const ulonglong2*)(wCol + (kb * 4 + kk) * 128);
                float av0 = (kk == 0) ? a0.x : (kk == 1) ? a0.y : (kk == 2) ? a0.z : a0.w;
                float av1 = (kk == 0) ? a1.x : (kk == 1) ? a1.y : (kk == 2) ? a1.z : a1.w;
                u64 ad0 = dup2(av0);
                u64 ad1 = dup2(av1);
                accFI0 = ffma2(ad0, wv.x, accFI0);
                accCO0 = ffma2(ad0, wv.y, accCO0);
                accFI1 = ffma2(ad1, wv.x, accFI1);
                accCO1 = ffma2(ad1, wv.y, accCO1);
            }
        }

        // epilogue: activations + state update + publish (no reduction)
        {
            float fs, is2, cs2, os2;
            unpack2f(accFI0, fs, is2); unpack2f(accCO0, cs2, os2);
            float fg = sigmoidf_(fs), ig = sigmoidf_(is2), og = sigmoidf_(os2);
            float ch = tanhf_(cs2);
            float cn = fg * c0 + ig * ch;
            float hn = og * tanhf_(cn);
            if (t < len0) { c0 = cn; h0 = hn; }
            hnext[(size_t)(b0 + r0) * HID + jg] = h0;

            unpack2f(accFI1, fs, is2); unpack2f(accCO1, cs2, os2);
            fg = sigmoidf_(fs); ig = sigmoidf_(is2); og = sigmoidf_(os2);
            ch = tanhf_(cs2);
            cn = fg * c1 + ig * ch;
            hn = og * tanhf_(cn);
            if (t < len1) { c1 = cn; h1 = hn; }
            hnext[(size_t)(b0 + r1) * HID + jg] = h1;
        }

        // row-group barrier (8 arrivals), release/acquire
        __syncthreads();
        if (tid == 0) {
            arrive_release(myctr);
            wait_target(myctr, 8u * (unsigned)(t + 1));
        }
        __syncthreads();
    }

    // global barrier before tail (tail reads arbitrary h rows)
    if (tid == 0) {
        arrive_release(&g_bar);
        wait_target(&g_bar, (unsigned)NCTA_S);
    }
    __syncthreads();

    // tail: y = h @ Wy + by, then copy h
    const float* __restrict__ hfin = g_hbuf[0];
    if (bid < 64) {
        const int row = bid * 4 + (tid >> 6);
        const int oc  = tid & 63;
        const float* hr = hfin + (size_t)row * HID;
        float acc = by[oc];
        #pragma unroll 4
        for (int k4 = 0; k4 < HID / 4; ++k4) {
            float4 hv = __ldcg((const float4*)(hr + k4 * 4));
            const float* wp = Wy + (size_t)k4 * 4 * OUTD + oc;
            acc += hv.x * wp[0] + hv.y * wp[OUTD] + hv.z * wp[2 * OUTD] + hv.w * wp[3 * OUTD];
        }
        out[(size_t)row * OUTD + oc] = acc;
    }
    {
        int idx = bid * 256 + tid;
        if (idx < BSZ * HID / 4) {
            float4 v = __ldcg(((const float4*)hfin) + idx);
            ((float4*)(out + BSZ * OUTD))[idx] = v;
        }
    }
}

extern "C" void kernel_launch(void* const* d_in, const int* in_sizes, int n_in,
                              void* d_out, int out_size) {
    const float* x       = (const float*)d_in[0];
    const int*   lengths = (const int*)  d_in[1];
    const float* Wf = (const float*)d_in[2];  const float* bf = (const float*)d_in[3];
    const float* Wi = (const float*)d_in[4];  const float* bi = (const float*)d_in[5];
    const float* Wc = (const float*)d_in[6];  const float* bc = (const float*)d_in[7];
    const float* Wo = (const float*)d_in[8];  const float* bo = (const float*)d_in[9];
    const float* Wy = (const float*)d_in[10]; const float* by = (const float*)d_in[11];
    float* out = (float*)d_out;

    cudaFuncSetAttribute(xw_mma, cudaFuncAttributeMaxDynamicSharedMemorySize, SMEM_MMA);
    cudaFuncSetAttribute(lstm_serial, cudaFuncAttributeMaxDynamicSharedMemorySize, SMEM_SERIAL);

    convert_x<<<(MROWS * DIN / 4) / 256, 256>>>(x);
    convert_w<<<1024, 256>>>(Wf, Wi, Wc, Wo);
    xw_mma<<<dim3(8, MROWS / 128), 256, SMEM_MMA>>>(bf, bi, bc, bo);
    init_state<<<64, 256>>>();
    lstm_serial<<<NCTA_S, 256, SMEM_SERIAL>>>(lengths, Wf, Wi, Wc, Wo, Wy, by, out);
}

// round 10
// speedup vs baseline: 1.5702x; 1.5702x over previous
#include <cuda_runtime.h>
#include <cuda_bf16.h>
#include <cstdint>
#include <cstring>

#define TS   512
#define BSZ  256
#define DIN  256
#define HID  256
#define OUTD 64
#define MROWS (TS * BSZ)
#define NCTA_S 128           // serial: 8 row-groups x 16 col-CTAs
#define PAK  40              // staged tile pitch in bf16 (80B rows: ldmatrix conflict-free)

// xw_mma smem layout (bytes)
#define OFF_BIAS 0
#define OFF_AH   1024
#define OFF_AL   (OFF_AH + 128 * PAK * 2)
#define OFF_BH   (OFF_AL + 128 * PAK * 2)
#define OFF_BL   (OFF_BH + 128 * PAK * 2)
#define SMEM_MMA (OFF_BL + 128 * PAK * 2)      // 41984 B

// serial smem layout (bytes): A 32rx256k hi/lo, W 64nx256k hi/lo, pitch 80B, 8 k-chunks
#define S_AH  0
#define S_AL  20480            // 8 * 32*80
#define S_WH  40960
#define S_WL  (S_WH + 40960)   // 8 * 64*80 each
#define S_EP  (S_WL + 40960)   // 122880; fp32 [32][68]
#define SMEM_SER (S_EP + 32 * 68 * 4)   // 131584 B

extern __shared__ char smem_dyn[];

__device__ float          g_xwb[(size_t)MROWS * 1024];   // x@Wx + b, [m][g*256+j]
__device__ __nv_bfloat16  g_ah[(size_t)MROWS * DIN];
__device__ __nv_bfloat16  g_al[(size_t)MROWS * DIN];
__device__ __nv_bfloat16  g_wth[1024 * 256];              // W^T hi [n][k]
__device__ __nv_bfloat16  g_wtl[1024 * 256];              // W^T lo
__device__ float          g_hbuf[2][BSZ * HID];
__device__ unsigned       g_rbar[16][64];                 // per-row-group barriers
__device__ unsigned       g_bar;                          // final global barrier

typedef unsigned long long u64;

__device__ __forceinline__ float sigmoidf_(float x) { return 1.0f / (1.0f + __expf(-x)); }
__device__ __forceinline__ float tanhf_(float x) {
    float e = __expf(2.0f * x); return 1.0f - 2.0f / (e + 1.0f);
}
__device__ __forceinline__ uint32_t s2u(const void* p) {
    uint32_t a; asm("{ .reg .u64 t; cvta.to.shared.u64 t, %1; cvt.u32.u64 %0, t; }" : "=r"(a) : "l"(p));
    return a;
}
__device__ __forceinline__ uint32_t pack2(float a, float b) {
    __nv_bfloat162 t; t.x = __float2bfloat16(a); t.y = __float2bfloat16(b);
    uint32_t r; memcpy(&r, &t, 4); return r;
}
__device__ __forceinline__ float rebf(float v) {
    return __bfloat162float(__float2bfloat16(v));
}
__device__ __forceinline__ void arrive_release(unsigned* ctr) {
    asm volatile("red.release.gpu.global.add.u32 [%0], %1;" :: "l"(ctr), "r"(1u) : "memory");
}
__device__ __forceinline__ void wait_target(const unsigned* ctr, unsigned tgt) {
    unsigned v;
    do {
        asm volatile("ld.global.acquire.gpu.u32 %0, [%1];" : "=r"(v) : "l"(ctr));
        if (v >= tgt) break;
        __nanosleep(20);
    } while (true);
}

#define LDSM4(d0, d1, d2, d3, addr) \
    asm volatile("ldmatrix.sync.aligned.m8n8.x4.shared.b16 {%0,%1,%2,%3}, [%4];" \
                 : "=r"(d0), "=r"(d1), "=r"(d2), "=r"(d3) : "r"(addr))

#define MMA16816(c, a, b0, b1) \
    asm volatile("mma.sync.aligned.m16n8k16.row.col.f32.bf16.bf16.f32 " \
                 "{%0,%1,%2,%3}, {%4,%5,%6,%7}, {%8,%9}, {%0,%1,%2,%3};" \
                 : "+f"((c)[0]), "+f"((c)[1]), "+f"((c)[2]), "+f"((c)[3]) \
                 : "r"((a)[0]), "r"((a)[1]), "r"((a)[2]), "r"((a)[3]), "r"(b0), "r"(b1))

// ---------------- conversions ----------------
__global__ void convert_x(const float* __restrict__ x) {
    size_t i = (size_t)blockIdx.x * 256 + threadIdx.x;
    float4 v = ((const float4*)x)[i];
    uint2 ph, pl;
    ph.x = pack2(v.x, v.y); ph.y = pack2(v.z, v.w);
    pl.x = pack2(v.x - rebf(v.x), v.y - rebf(v.y));
    pl.y = pack2(v.z - rebf(v.z), v.w - rebf(v.w));
    ((uint2*)g_ah)[i] = ph;
    ((uint2*)g_al)[i] = pl;
}

__global__ void convert_w(const float* __restrict__ Wf, const float* __restrict__ Wi,
                          const float* __restrict__ Wc, const float* __restrict__ Wo) {
    int n = blockIdx.x, k = threadIdx.x;
    int g = n >> 8, j = n & 255;
    const float* Wg = (g == 0) ? Wf : (g == 1) ? Wi : (g == 2) ? Wc : Wo;
    float v = Wg[(size_t)k * HID + j];
    g_wth[n * 256 + k] = __float2bfloat16(v);
    g_wtl[n * 256 + k] = __float2bfloat16(v - rebf(v));
}

// ---------------- xwb = x @ Wx + b via mma.sync bf16 3-term split ----------------
__global__ void __launch_bounds__(256) xw_mma(
    const float* __restrict__ bfp, const float* __restrict__ bip,
    const float* __restrict__ bcp, const float* __restrict__ bop)
{
    char* sm = smem_dyn;
    float* sBias = (float*)(sm + OFF_BIAS);
    const uint32_t uAh = s2u(sm + OFF_AH);
    const uint32_t uAl = s2u(sm + OFF_AL);
    const uint32_t uBh = s2u(sm + OFF_BH);
    const uint32_t uBl = s2u(sm + OFF_BL);

    const int tid  = threadIdx.x;
    const int w    = tid >> 5;
    const int lane = tid & 31;
    const int wm   = w & 3;
    const int wn   = w >> 2;
    const int n0   = blockIdx.x * 128;
    const int m0   = blockIdx.y * 128;

    if (tid < 128) {
        int g = n0 >> 8;
        const float* bg = (g == 0) ? bfp : (g == 1) ? bip : (g == 2) ? bcp : bop;
        sBias[tid] = bg[(n0 & 255) + tid];
    }

    const int arow  = lane & 15;
    const int ahalf = (lane >> 4) & 1;
    const int brow  = ((lane >> 4) & 1) * 8 + (lane & 7);
    const int bcol  = ((lane >> 3) & 1) * 8;

    float c[2][8][4];
    #pragma unroll
    for (int mt = 0; mt < 2; ++mt)
        #pragma unroll
        for (int nt = 0; nt < 8; ++nt)
            #pragma unroll
            for (int q = 0; q < 4; ++q) c[mt][nt][q] = 0.f;

    for (int ck = 0; ck < 8; ++ck) {
        const int k0 = ck * 32;
        __syncthreads();
        #pragma unroll
        for (int it = 0; it < 2; ++it) {
            int idx = tid + it * 256;
            int r = idx >> 2, cq = idx & 3;
            uint32_t doff = (uint32_t)(r * (PAK * 2) + cq * 16);
            *(uint4*)(sm + OFF_AH + doff) = *(const uint4*)(g_ah  + (size_t)(m0 + r) * 256 + k0 + cq * 8);
            *(uint4*)(sm + OFF_AL + doff) = *(const uint4*)(g_al  + (size_t)(m0 + r) * 256 + k0 + cq * 8);
            *(uint4*)(sm + OFF_BH + doff) = *(const uint4*)(g_wth + (size_t)(n0 + r) * 256 + k0 + cq * 8);
            *(uint4*)(sm + OFF_BL + doff) = *(const uint4*)(g_wtl + (size_t)(n0 + r) * 256 + k0 + cq * 8);
        }
        __syncthreads();

        #pragma unroll
        for (int ks = 0; ks < 2; ++ks) {
            const int kk = ks * 16;
            uint32_t ah[2][4], al[2][4];
            #pragma unroll
            for (int mt = 0; mt < 2; ++mt) {
                uint32_t ao = (uint32_t)((wm * 32 + mt * 16 + arow) * (PAK * 2) + (kk + ahalf * 8) * 2);
                LDSM4(ah[mt][0], ah[mt][1], ah[mt][2], ah[mt][3], uAh + ao);
                LDSM4(al[mt][0], al[mt][1], al[mt][2], al[mt][3], uAl + ao);
            }
            #pragma unroll
            for (int np = 0; np < 4; ++np) {
                uint32_t bo = (uint32_t)((wn * 64 + np * 16 + brow) * (PAK * 2) + (kk + bcol) * 2);
                uint32_t bh[4], bl[4];
                LDSM4(bh[0], bh[1], bh[2], bh[3], uBh + bo);
                LDSM4(bl[0], bl[1], bl[2], bl[3], uBl + bo);
                #pragma unroll
                for (int mt = 0; mt < 2; ++mt) {
                    MMA16816(c[mt][2 * np],     ah[mt], bh[0], bh[1]);
                    MMA16816(c[mt][2 * np + 1], ah[mt], bh[2], bh[3]);
                    MMA16816(c[mt][2 * np],     ah[mt], bl[0], bl[1]);
                    MMA16816(c[mt][2 * np + 1], ah[mt], bl[2], bl[3]);
                    MMA16816(c[mt][2 * np],     al[mt], bh[0], bh[1]);
                    MMA16816(c[mt][2 * np + 1], al[mt], bh[2], bh[3]);
                }
            }
        }
    }

    const int g  = lane >> 2;
    const int tg = lane & 3;
    float* base = g_xwb + (size_t)(m0 + wm * 32) * 1024 + n0 + wn * 64;
    #pragma unroll
    for (int mt = 0; mt < 2; ++mt) {
        #pragma unroll
        for (int nt = 0; nt < 8; ++nt) {
            float2 bv = *(float2*)&sBias[wn * 64 + nt * 8 + 2 * tg];
            float2 v0, v1;
            v0.x = c[mt][nt][0] + bv.x; v0.y = c[mt][nt][1] + bv.y;
            v1.x = c[mt][nt][2] + bv.x; v1.y = c[mt][nt][3] + bv.y;
            *(float2*)(base + (size_t)(mt * 16 + g)     * 1024 + nt * 8 + 2 * tg) = v0;
            *(float2*)(base + (size_t)(mt * 16 + g + 8) * 1024 + nt * 8 + 2 * tg) = v1;
        }
    }
}

// ---------------- init ----------------
__global__ void init_state() {
    int i = blockIdx.x * blockDim.x + threadIdx.x;
    if (i == 0) g_bar = 0u;
    if (i < 16 * 64) ((unsigned*)g_rbar)[i] = 0u;
    if (i < BSZ * HID / 4) ((float4*)g_hbuf[0])[i] = make_float4(0.f, 0.f, 0.f, 0.f);
}

// ---------------- serial loop: h @ Wh via mma.sync bf16 3-term split ----------------
// 128 CTAs = 8 row-groups(32 rows) x 16 col-CTAs(16 hcols x 4 gates = N64).
// 8 warps = 2 m16 x 4 n16, full K=256 per warp (no cross-warp reduction).
__global__ void __launch_bounds__(256, 1) lstm_serial(
    const int* __restrict__ lengths,
    const float* __restrict__ Wf, const float* __restrict__ Wi,
    const float* __restrict__ Wc, const float* __restrict__ Wo,
    const float* __restrict__ Wy, const float* __restrict__ by,
    float* __restrict__ out)
{
    char* sm = smem_dyn;
    const uint32_t uBase = s2u(sm);
    float* sEp = (float*)(sm + S_EP);      // [32][68] fp32

    const int tid  = threadIdx.x;
    const int w    = tid >> 5;
    const int lane = tid & 31;
    const int mt   = w >> 2;          // 0/1 -> rows mt*16..
    const int nt   = w & 3;           // n16 block
    const int bid  = blockIdx.x;
    const int grp  = bid >> 4;        // 8 groups of 32 rows
    const int b0   = grp * 32;
    const int j0   = (bid & 15) * 16;
    unsigned* myctr = &g_rbar[grp][0];

    // ---- stage W hi/lo once: sW[n=gate*16+jj][k], pitch 80B, 8 k-chunks ----
    for (int i = tid; i < 64 * 256; i += 256) {
        int n = i & 63, k = i >> 6;
        int g = n >> 4, jj = n & 15;
        const float* __restrict__ Wg = (g == 0) ? Wf : (g == 1) ? Wi : (g == 2) ? Wc : Wo;
        float v = Wg[(size_t)(DIN + k) * HID + j0 + jj];
        int ck = k >> 5, kk = k & 31;
        uint32_t off = (uint32_t)(ck * 5120 + n * 80 + kk * 2);
        *(__nv_bfloat16*)(sm + S_WH + off) = __float2bfloat16(v);
        *(__nv_bfloat16*)(sm + S_WL + off) = __float2bfloat16(v - rebf(v));
    }

    // epilogue ownership: thread -> (rows tid>>4 and +16, col jj0)
    const int row0 = tid >> 4, jj0 = tid & 15;
    const int row1 = row0 + 16;
    const int lenA = lengths[b0 + row0];
    const int lenB = lengths[b0 + row1];
    float cA = 0.f, cB = 0.f, hA = 0.f, hB = 0.f;

    const int arow  = lane & 15;
    const int ahalf = (lane >> 4) & 1;
    const int brow  = ((lane >> 4) & 1) * 8 + (lane & 7);
    const int bcol  = ((lane >> 3) & 1) * 8;
    const int gl    = lane >> 2;
    const int tg    = lane & 3;

    for (int t = 0; t < TS; ++t) {
        const float* __restrict__ hprev = g_hbuf[t & 1];
        float*       __restrict__ hnext = g_hbuf[(t + 1) & 1];

        // prefetch xW+b for both owned (b,j) pairs
        const float* xA = g_xwb + ((size_t)t * BSZ + b0 + row0) * 1024 + j0 + jj0;
        const float* xB = g_xwb + ((size_t)t * BSZ + b0 + row1) * 1024 + j0 + jj0;
        float pfA = __ldcg(xA), piA = __ldcg(xA + 256), pcA = __ldcg(xA + 512), poA = __ldcg(xA + 768);
        float pfB = __ldcg(xB), piB = __ldcg(xB + 256), pcB = __ldcg(xB + 512), poB = __ldcg(xB + 768);

        // ---- stage h rows b0..b0+31 as bf16 hi/lo ----
        #pragma unroll
        for (int it = 0; it < 8; ++it) {
            int idx = tid + it * 256;
            int r = idx >> 6, c4 = idx & 63;
            int k = c4 * 4, ck = k >> 5, kk = k & 31;
            float4 v = __ldcg((const float4*)(hprev + (size_t)(b0 + r) * HID + k));
            uint2 hi, lo;
            hi.x = pack2(v.x, v.y); hi.y = pack2(v.z, v.w);
            lo.x = pack2(v.x - rebf(v.x), v.y - rebf(v.y));
            lo.y = pack2(v.z - rebf(v.z), v.w - rebf(v.w));
            uint32_t off = (uint32_t)(ck * 2560 + r * 80 + kk * 2);
            *(uint2*)(sm + S_AH + off) = hi;
            *(uint2*)(sm + S_AL + off) = lo;
        }
        __syncthreads();

        // ---- MMA: warp (mt, nt), full K=256, 3-term split ----
        float c0[4] = {0.f, 0.f, 0.f, 0.f};
        float c1[4] = {0.f, 0.f, 0.f, 0.f};
        #pragma unroll
        for (int ck = 0; ck < 8; ++ck) {
            #pragma unroll
            for (int ks = 0; ks < 2; ++ks) {
                const int kk = ks * 16;
                uint32_t ah[4], al[4], bh[4], bl[4];
                uint32_t ao = uBase + (uint32_t)(ck * 2560 + (mt * 16 + arow) * 80 + (kk + ahalf * 8) * 2);
                LDSM4(ah[0], ah[1], ah[2], ah[3], ao + S_AH);
                LDSM4(al[0], al[1], al[2], al[3], ao + S_AL);
                uint32_t bo = uBase + (uint32_t)(ck * 5120 + (nt * 16 + brow) * 80 + (kk + bcol) * 2);
                LDSM4(bh[0], bh[1], bh[2], bh[3], bo + S_WH);
                LDSM4(bl[0], bl[1], bl[2], bl[3], bo + S_WL);
                MMA16816(c0, ah, bh[0], bh[1]);
                MMA16816(c1, ah, bh[2], bh[3]);
                MMA16816(c0, ah, bl[0], bl[1]);
                MMA16816(c1, ah, bl[2], bl[3]);
                MMA16816(c0, al, bh[0], bh[1]);
                MMA16816(c1, al, bh[2], bh[3]);
            }
        }

        // ---- acc -> smem exchange ----
        {
            int r = mt * 16 + gl;
            float* e = sEp + r * 68 + nt * 16 + 2 * tg;
            *(float2*)(e)            = make_float2(c0[0], c0[1]);
            *(float2*)(e + 8)        = make_float2(c1[0], c1[1]);
            float* e8 = sEp + (r + 8) * 68 + nt * 16 + 2 * tg;
            *(float2*)(e8)           = make_float2(c0[2], c0[3]);
            *(float2*)(e8 + 8)       = make_float2(c1[2], c1[3]);
        }
        __syncthreads();

        // ---- epilogue: gates + state update + publish h ----
        {
            const float* eA = sEp + row0 * 68 + jj0;
            float fg = sigmoidf_(eA[0]  + pfA);
            float ig = sigmoidf_(eA[16] + piA);
            float ch = tanhf_(eA[32] + pcA);
            float og = sigmoidf_(eA[48] + poA);
            float cn = fg * cA + ig * ch;
            float hn = og * tanhf_(cn);
            if (t < lenA) { cA = cn; hA = hn; }
            hnext[(size_t)(b0 + row0) * HID + j0 + jj0] = hA;

            const float* eB = sEp + row1 * 68 + jj0;
            fg = sigmoidf_(eB[0]  + pfB);
            ig = sigmoidf_(eB[16] + piB);
            ch = tanhf_(eB[32] + pcB);
            og = sigmoidf_(eB[48] + poB);
            cn = fg * cB + ig * ch;
            hn = og * tanhf_(cn);
            if (t < lenB) { cB = cn; hB = hn; }
            hnext[(size_t)(b0 + row1) * HID + j0 + jj0] = hB;
        }

        // ---- row-group barrier (16 arrivals) ----
        __syncthreads();
        if (tid == 0) {
            arrive_release(myctr);
            wait_target(myctr, 16u * (unsigned)(t + 1));
        }
        __syncthreads();
    }

    // global barrier before tail
    if (tid == 0) {
        arrive_release(&g_bar);
        wait_target(&g_bar, (unsigned)NCTA_S);
    }
    __syncthreads();

    // tail: y = h @ Wy + by, then copy h
    const float* __restrict__ hfin = g_hbuf[0];
    if (bid < 64) {
        const int row = bid * 4 + (tid >> 6);
        const int oc  = tid & 63;
        const float* hr = hfin + (size_t)row * HID;
        float acc = by[oc];
        #pragma unroll 4
        for (int k4 = 0; k4 < HID / 4; ++k4) {
            float4 hv = __ldcg((const float4*)(hr + k4 * 4));
            const float* wp = Wy + (size_t)k4 * 4 * OUTD + oc;
            acc += hv.x * wp[0] + hv.y * wp[OUTD] + hv.z * wp[2 * OUTD] + hv.w * wp[3 * OUTD];
        }
        out[(size_t)row * OUTD + oc] = acc;
    }
    {
        int idx = bid * 256 + tid;
        if (idx < BSZ * HID / 4) {
            float4 v = __ldcg(((const float4*)hfin) + idx);
            ((float4*)(out + BSZ * OUTD))[idx] = v;
        }
    }
}

extern "C" void kernel_launch(void* const* d_in, const int* in_sizes, int n_in,
                              void* d_out, int out_size) {
    const float* x       = (const float*)d_in[0];
    const int*   lengths = (const int*)  d_in[1];
    const float* Wf = (const float*)d_in[2];  const float* bf = (const float*)d_in[3];
    const float* Wi = (const float*)d_in[4];  const float* bi = (const float*)d_in[5];
    const float* Wc = (const float*)d_in[6];  const float* bc = (const float*)d_in[7];
    const float* Wo = (const float*)d_in[8];  const float* bo = (const float*)d_in[9];
    const float* Wy = (const float*)d_in[10]; const float* by = (const float*)d_in[11];
    float* out = (float*)d_out;

    cudaFuncSetAttribute(xw_mma, cudaFuncAttributeMaxDynamicSharedMemorySize, SMEM_MMA);
    cudaFuncSetAttribute(lstm_serial, cudaFuncAttributeMaxDynamicSharedMemorySize, SMEM_SER);

    convert_x<<<(MROWS * DIN / 4) / 256, 256>>>(x);
    convert_w<<<1024, 256>>>(Wf, Wi, Wc, Wo);
    xw_mma<<<dim3(8, MROWS / 128), 256, SMEM_MMA>>>(bf, bi, bc, bo);
    init_state<<<64, 256>>>();
    lstm_serial<<<NCTA_S, 256, SMEM_SER>>>(lengths, Wf, Wi, Wc, Wo, Wy, by, out);
}